// round 11
// baseline (speedup 1.0000x reference)
#include <cuda_runtime.h>
#include <cuda_fp16.h>
#include <cstdint>

#define MM 128
#define DD 5
#define FA 62
#define FB 6
#define FAN 68
#define CC 128
#define KP 88            /* A-tile K stride in halves (176B, conflict-free ldmatrix) */

// ---- smem byte offsets ----
#define SB_SB    0                      /* s_sb   f32 [128][6]  = 3072  */
#define SB_DEG   3072                   /* s_deg  int [128]     = 512   */
#define SB_XBUF  3584                   /* s_xbuf f32 [8][68]   = 2176  */
#define SB_A     5760                   /* u16 [128][88] = 22528 */
#define SMEM_BYTES (SB_A + 22528)       /* 28288 B */

typedef unsigned int u32;
typedef unsigned short u16;
typedef unsigned long long u64;

// Pre-packed fp16 B fragments: index = (kt*16 + n8)*32 + lane ; kt in [0,5), n8 in [0,16)
__device__ u64 g_bf[2560];

__device__ __forceinline__ uint32_t smem_u32(const void* p) {
    uint32_t a;
    asm("{ .reg .u64 t; cvta.to.shared.u64 t, %1; cvt.u32.u64 %0, t; }" : "=r"(a) : "l"(p));
    return a;
}
__device__ __forceinline__ uint4 ldm_x4(uint32_t addr) {
    uint4 r;
    asm volatile("ldmatrix.sync.aligned.m8n8.x4.shared.b16 {%0,%1,%2,%3}, [%4];"
                 : "=r"(r.x), "=r"(r.y), "=r"(r.z), "=r"(r.w) : "r"(addr));
    return r;
}
__device__ __forceinline__ void mma_f16(float4& c, const uint4& a, u32 b0, u32 b1) {
    asm volatile(
        "mma.sync.aligned.m16n8k16.row.col.f32.f16.f16.f32 "
        "{%0,%1,%2,%3},{%4,%5,%6,%7},{%8,%9},{%0,%1,%2,%3};"
        : "+f"(c.x), "+f"(c.y), "+f"(c.z), "+f"(c.w)
        : "r"(a.x), "r"(a.y), "r"(a.z), "r"(a.w), "r"(b0), "r"(b1));
}
__device__ __forceinline__ u16 h16(float v) {
    return __half_as_ushort(__float2half_rn(v));
}
__device__ __forceinline__ float f16f(u16 v) {
    return __half2float(__ushort_as_half(v));
}
__device__ __forceinline__ u32 pairh(float a, float b) {
    const __half2 h = __floats2half2_rn(a, b);
    return *(const u32*)&h;
}

// ---- setup kernel: pack Ws|bs into fragment-ordered fp16 ----
__global__ void pack_b_kernel(const float* __restrict__ Ws, const float* __restrict__ bs) {
    const int idx = blockIdx.x * blockDim.x + threadIdx.x;
    if (idx >= 2560) return;
    const int l    = idx & 31;
    const int tile = idx >> 5;         // kt*16 + n8
    const int kt   = tile >> 4;
    const int n8   = tile & 15;
    const int c    = l >> 2, t = l & 3;
    const int n    = n8 * 8 + c;
    const int k0   = kt * 16 + 2 * t;
    const int ks[4] = { k0, k0 + 1, k0 + 8, k0 + 9 };
    u16 h[4];
    #pragma unroll
    for (int q = 0; q < 4; q++) {
        const int k = ks[q];
        float v = 0.f;
        if (k < FAN)       v = Ws[k * CC + n];
        else if (k == FAN) v = bs[n];
        h[q] = h16(v);
    }
    g_bf[idx] = (u64)((u32)h[0] | ((u32)h[1] << 16))
              | ((u64)((u32)h[2] | ((u32)h[3] << 16)) << 32);
}

__global__ __launch_bounds__(256, 5)
void tga_kernel(const float* __restrict__ atoms,
                const float* __restrict__ bonds,
                const int*   __restrict__ edges,
                const float* __restrict__ Wi,   // (D, FAN, CC)
                const float* __restrict__ bi,   // (D, CC)
                float* __restrict__ out)        // (B, MM, CC)
{
    extern __shared__ char smem[];
    float* s_sb   = (float*)(smem + SB_SB);     // summed bonds [128][6]
    int*   s_deg  = (int*)(smem + SB_DEG);
    float* s_xbuf = (float*)(smem + SB_XBUF);   // per-warp X scratch [8][68]
    u16*   aF     = (u16*)(smem + SB_A);        // V tile fp16 [128][KP]

    const int b    = blockIdx.x;
    const int tid  = threadIdx.x;
    const int w    = tid >> 5;
    const int lane = tid & 31;

    const float* ga = atoms + (size_t)b * (MM * FA);
    const float* gb = bonds + (size_t)b * (MM * DD * FB);
    const int*   ge = edges + (size_t)b * (MM * DD);

    // ---- phase 1a: summed bonds (coalesced row loads + shfl reduce) + degree ----
    {
        const u32 full = 0xFFFFFFFFu;
        #pragma unroll 1
        for (int i = 0; i < 16; i++) {
            const int m = w * 16 + i;
            float v = 0.f;
            if (lane < 30) v = gb[m * (DD * FB) + lane];
            float t = v;
            t += __shfl_down_sync(full, t, 6);
            t += __shfl_down_sync(full, t, 12);
            t += __shfl_down_sync(full, v, 24);
            if (lane < FB) s_sb[m * FB + lane] = t;
        }
    }
    if (tid < MM) {
        const int* ep = ge + tid * DD;
        s_deg[tid] = (ep[0] >= 0) + (ep[1] >= 0) + (ep[2] >= 0) + (ep[3] >= 0) + (ep[4] >= 0);
    }
    __syncwarp();

    // ---- phase 1b: A tile (coalesced): V = [atoms | summed_bonds | 1 | 0...] ----
    {
        #pragma unroll 1
        for (int i = 0; i < 16; i++) {
            const int m = w * 16 + i;
            if (lane < 31) {
                const float2 x = ((const float2*)(ga + m * FA))[lane];
                *(u32*)(aF + m * KP + 2 * lane) = pairh(x.x, x.y);   // cols 0..61
            }
        }
        __syncwarp();
        // tail cols 62..87: 2 lanes per row
        const int mr = w * 16 + (lane >> 1);
        u64* arow = (u64*)(aF + mr * KP);
        const float* sb = s_sb + mr * FB;
        if ((lane & 1) == 0) {
            arow[16] = (u64)pairh(sb[2], sb[3]) | ((u64)pairh(sb[4], sb[5]) << 32); // 64..67
            arow[18] = 0;  arow[20] = 0;
        } else {
            *(u32*)(aF + mr * KP + 62) = pairh(sb[0], sb[1]);        // cols 62,63
            arow[17] = 0x3C00ull;                                    // col 68 = 1.0
            arow[19] = 0;  arow[21] = 0;
        }
    }
    __syncthreads();

    // ---- phase 2: warp w -> rows [16w,16w+16); A frags hoisted; 8 col-strips of 16 ----
    const int m0 = w * 16;
    const u32 aAddr = smem_u32(aF);
    const int aRow = m0 + (lane & 7) + ((lane >> 3) & 1) * 8;
    const int aColOff = (lane >> 4) * 8;
    float* ob = out + (size_t)b * (MM * CC);
    const int rLo = m0 + (lane >> 2);
    const int rHi = rLo + 8;
    const int t2  = 2 * (lane & 3);

    uint4 afr[5];
    #pragma unroll
    for (int kt = 0; kt < 5; kt++)
        afr[kt] = ldm_x4(aAddr + (aRow * KP + kt * 16 + aColOff) * 2);

    #pragma unroll 1
    for (int s = 0; s < 8; s++) {
        float4 acc0 = make_float4(0.f, 0.f, 0.f, 0.f);
        float4 acc1 = make_float4(0.f, 0.f, 0.f, 0.f);
        const u64* bp = g_bf + s * 64 + lane;
        #pragma unroll
        for (int kt = 0; kt < 5; kt++) {
            const u64 v0 = bp[kt * 512];
            const u64 v1 = bp[kt * 512 + 32];
            mma_f16(acc0, afr[kt], (u32)v0, (u32)(v0 >> 32));
            mma_f16(acc1, afr[kt], (u32)v1, (u32)(v1 >> 32));
        }
        // epilogue strip: relu + direct store (cols 16s .. 16s+15)
        const int c0 = s * 16 + t2;
        float2 p;
        p.x = fmaxf(acc0.x, 0.f); p.y = fmaxf(acc0.y, 0.f);
        *(float2*)(ob + rLo * CC + c0) = p;
        p.x = fmaxf(acc0.z, 0.f); p.y = fmaxf(acc0.w, 0.f);
        *(float2*)(ob + rHi * CC + c0) = p;
        p.x = fmaxf(acc1.x, 0.f); p.y = fmaxf(acc1.y, 0.f);
        *(float2*)(ob + rLo * CC + c0 + 8) = p;
        p.x = fmaxf(acc1.z, 0.f); p.y = fmaxf(acc1.w, 0.f);
        *(float2*)(ob + rHi * CC + c0 + 8) = p;
    }
    __syncwarp();

    // ---- phase 3: rare inner matvec (deg<5 only, ~3.8% of nodes) ----
    for (int mi = 0; mi < 16; mi++) {
        const int m = w * 16 + mi;
        const int deg = s_deg[m];            // warp-uniform
        if (deg < DD) {
            const int e0 = ge[m*DD+0], e1 = ge[m*DD+1], e2 = ge[m*DD+2],
                      e3 = ge[m*DD+3], e4 = ge[m*DD+4];
            // build X = [summed_atoms | summed_bonds] in per-warp scratch
            #pragma unroll
            for (int rep = 0; rep < 3; rep++) {
                const int f = lane + rep * 32;
                if (f < FA) {
                    float s = 0.f;
                    if (e0 >= 0) s += f16f(aF[e0*KP + f]);
                    if (e1 >= 0) s += f16f(aF[e1*KP + f]);
                    if (e2 >= 0) s += f16f(aF[e2*KP + f]);
                    if (e3 >= 0) s += f16f(aF[e3*KP + f]);
                    if (e4 >= 0) s += f16f(aF[e4*KP + f]);
                    s_xbuf[w * FAN + f] = s;
                } else if (f < FAN) {
                    s_xbuf[w * FAN + f] = s_sb[m * FB + (f - FA)];
                }
            }
            __syncwarp();
            const int c = lane * 4;
            const float* wp = Wi + ((size_t)deg * FAN) * CC + c;
            float4 acc = *(const float4*)(bi + deg * CC + c);
            const float* xr = s_xbuf + w * FAN;
            #pragma unroll 4
            for (int k = 0; k < FAN; k++) {
                const float xv = xr[k];
                const float4 w4 = *(const float4*)(wp + k * CC);
                acc.x += xv * w4.x; acc.y += xv * w4.y;
                acc.z += xv * w4.z; acc.w += xv * w4.w;
            }
            float4* outp = (float4*)(out + ((size_t)b * MM + m) * CC + c);
            float4 o = *outp;
            o.x += fmaxf(acc.x, 0.f); o.y += fmaxf(acc.y, 0.f);
            o.z += fmaxf(acc.z, 0.f); o.w += fmaxf(acc.w, 0.f);
            *outp = o;
            __syncwarp();
        }
    }
}

extern "C" void kernel_launch(void* const* d_in, const int* in_sizes, int n_in,
                              void* d_out, int out_size) {
    const float* atoms = (const float*)d_in[0];
    const float* bonds = (const float*)d_in[1];
    const int*   edges = (const int*)  d_in[2];
    const float* Wi    = (const float*)d_in[3];
    const float* bi    = (const float*)d_in[4];
    const float* Ws    = (const float*)d_in[5];
    const float* bs    = (const float*)d_in[6];
    float* out = (float*)d_out;

    const int B = in_sizes[0] / (MM * FA);

    pack_b_kernel<<<10, 256>>>(Ws, bs);

    cudaFuncSetAttribute(tga_kernel,
                         cudaFuncAttributeMaxDynamicSharedMemorySize, SMEM_BYTES);
    tga_kernel<<<B, 256, SMEM_BYTES>>>(atoms, bonds, edges, Wi, bi, out);
}

// round 12
// speedup vs baseline: 1.3764x; 1.3764x over previous
#include <cuda_runtime.h>
#include <cuda_fp16.h>
#include <cstdint>

#define MM 128
#define DD 5
#define FA 62
#define FB 6
#define FAN 68
#define CC 128
#define KP 88            /* A-tile K stride in halves (176B, conflict-free ldmatrix) */

// ---- smem byte offsets ----
#define SB_SB    0                      /* s_sb   f32 [128][6]  = 3072  */
#define SB_DEG   3072                   /* s_deg  int [128]     = 512   */
#define SB_XBUF  3584                   /* s_xbuf f32 [8][68]   = 2176  */
#define SB_A     5760                   /* u16 [128][88] = 22528 */
#define SMEM_BYTES (SB_A + 22528)       /* 28288 B */

typedef unsigned int u32;
typedef unsigned short u16;
typedef unsigned long long u64;

// Pre-packed fp16 B fragments (column-PERMUTED so epilogue stores are float4):
// index = (kt*16 + n8)*32 + lane ; strip s = n8>>1, tile j = n8&1, c = lane>>2
// logical col n = s*16 + (c>>1)*4 + j*2 + (c&1)
__device__ u64 g_bf[2560];

__device__ __forceinline__ uint32_t smem_u32(const void* p) {
    uint32_t a;
    asm("{ .reg .u64 t; cvta.to.shared.u64 t, %1; cvt.u32.u64 %0, t; }" : "=r"(a) : "l"(p));
    return a;
}
__device__ __forceinline__ uint4 ldm_x4(uint32_t addr) {
    uint4 r;
    asm volatile("ldmatrix.sync.aligned.m8n8.x4.shared.b16 {%0,%1,%2,%3}, [%4];"
                 : "=r"(r.x), "=r"(r.y), "=r"(r.z), "=r"(r.w) : "r"(addr));
    return r;
}
__device__ __forceinline__ void mma_f16(float4& c, const uint4& a, u32 b0, u32 b1) {
    asm volatile(
        "mma.sync.aligned.m16n8k16.row.col.f32.f16.f16.f32 "
        "{%0,%1,%2,%3},{%4,%5,%6,%7},{%8,%9},{%0,%1,%2,%3};"
        : "+f"(c.x), "+f"(c.y), "+f"(c.z), "+f"(c.w)
        : "r"(a.x), "r"(a.y), "r"(a.z), "r"(a.w), "r"(b0), "r"(b1));
}
__device__ __forceinline__ u16 h16(float v) {
    return __half_as_ushort(__float2half_rn(v));
}
__device__ __forceinline__ float f16f(u16 v) {
    return __half2float(__ushort_as_half(v));
}
__device__ __forceinline__ u32 pairh(float a, float b) {
    const __half2 h = __floats2half2_rn(a, b);
    return *(const u32*)&h;
}

// ---- setup kernel: pack Ws|bs into fragment-ordered fp16 (col-permuted) ----
__global__ void pack_b_kernel(const float* __restrict__ Ws, const float* __restrict__ bs) {
    const int idx = blockIdx.x * blockDim.x + threadIdx.x;
    if (idx >= 2560) return;
    const int l    = idx & 31;
    const int tile = idx >> 5;         // kt*16 + n8
    const int kt   = tile >> 4;
    const int n8   = tile & 15;
    const int s    = n8 >> 1;          // col strip (16 cols)
    const int j    = n8 & 1;           // tile within strip
    const int c    = l >> 2, t = l & 3;
    // permuted logical column: thread t owns 4 contiguous cols s*16+4t.. in the strip
    const int n    = s * 16 + (c >> 1) * 4 + j * 2 + (c & 1);
    const int k0   = kt * 16 + 2 * t;
    const int ks[4] = { k0, k0 + 1, k0 + 8, k0 + 9 };
    u16 h[4];
    #pragma unroll
    for (int q = 0; q < 4; q++) {
        const int k = ks[q];
        float v = 0.f;
        if (k < FAN)       v = Ws[k * CC + n];
        else if (k == FAN) v = bs[n];
        h[q] = h16(v);
    }
    g_bf[idx] = (u64)((u32)h[0] | ((u32)h[1] << 16))
              | ((u64)((u32)h[2] | ((u32)h[3] << 16)) << 32);
}

__global__ __launch_bounds__(256, 5)
void tga_kernel(const float* __restrict__ atoms,
                const float* __restrict__ bonds,
                const int*   __restrict__ edges,
                const float* __restrict__ Wi,   // (D, FAN, CC)
                const float* __restrict__ bi,   // (D, CC)
                float* __restrict__ out)        // (B, MM, CC)
{
    extern __shared__ char smem[];
    float* s_sb   = (float*)(smem + SB_SB);     // summed bonds [128][6]
    int*   s_deg  = (int*)(smem + SB_DEG);
    float* s_xbuf = (float*)(smem + SB_XBUF);   // per-warp X scratch [8][68]
    u16*   aF     = (u16*)(smem + SB_A);        // V tile fp16 [128][KP]

    const int b    = blockIdx.x;
    const int tid  = threadIdx.x;
    const int w    = tid >> 5;
    const int lane = tid & 31;

    const float* ga = atoms + (size_t)b * (MM * FA);
    const float* gb = bonds + (size_t)b * (MM * DD * FB);
    const int*   ge = edges + (size_t)b * (MM * DD);

    // ---- phase 1a: summed bonds + degree (R10 layout: high MLP) ----
    #pragma unroll
    for (int rep = 0; rep < 3; rep++) {
        const int i = rep * 256 + tid;
        const int m = i / FB, f = i - m * FB;
        const float* bp = gb + m * (DD * FB) + f;
        s_sb[i] = bp[0] + bp[6] + bp[12] + bp[18] + bp[24];
    }
    if (tid < MM) {
        const int* ep = ge + tid * DD;
        s_deg[tid] = (ep[0] >= 0) + (ep[1] >= 0) + (ep[2] >= 0) + (ep[3] >= 0) + (ep[4] >= 0);
    }
    __syncthreads();

    // ---- phase 1b: A tile, branch-free thread-per-row (R10: high MLP) ----
    {
        const int m = tid & 127;                   // row
        u64* arow = (u64*)(aF + m * KP);
        const float2* ap = (const float2*)(ga + m * FA);
        if (tid < 128) {
            // cols 0..43 (pure atoms): 11 u64
            #pragma unroll
            for (int j = 0; j < 11; j++) {
                const float2 x0 = ap[2 * j];
                const float2 x1 = ap[2 * j + 1];
                arow[j] = (u64)pairh(x0.x, x0.y) | ((u64)pairh(x1.x, x1.y) << 32);
            }
        } else {
            // cols 44..59 (atoms): 4 u64
            #pragma unroll
            for (int j = 0; j < 4; j++) {
                const float2 x0 = ap[22 + 2 * j];
                const float2 x1 = ap[23 + 2 * j];
                arow[11 + j] = (u64)pairh(x0.x, x0.y) | ((u64)pairh(x1.x, x1.y) << 32);
            }
            const float* sb = s_sb + m * FB;
            // cols 60..63: atoms 60,61 | bonds 0,1
            const float2 x0 = ap[30];
            arow[15] = (u64)pairh(x0.x, x0.y) | ((u64)pairh(sb[0], sb[1]) << 32);
            // cols 64..67: bonds 2..5
            arow[16] = (u64)pairh(sb[2], sb[3]) | ((u64)pairh(sb[4], sb[5]) << 32);
            // cols 68..71: bias one, zeros
            arow[17] = 0x3C00ull;                  // fp16 1.0 in col 68
            // cols 72..87: zeros
            arow[18] = 0; arow[19] = 0; arow[20] = 0; arow[21] = 0;
        }
    }
    __syncthreads();

    // ---- phase 2: warp w -> rows [16w,16w+16); A frags hoisted; 8 col-strips of 16 ----
    const int m0 = w * 16;
    const u32 aAddr = smem_u32(aF);
    const int aRow = m0 + (lane & 7) + ((lane >> 3) & 1) * 8;
    const int aColOff = (lane >> 4) * 8;
    float* ob = out + (size_t)b * (MM * CC);
    const int rLo = m0 + (lane >> 2);
    const int rHi = rLo + 8;
    const int t4  = 4 * (lane & 3);

    uint4 afr[5];
    #pragma unroll
    for (int kt = 0; kt < 5; kt++)
        afr[kt] = ldm_x4(aAddr + (aRow * KP + kt * 16 + aColOff) * 2);

    #pragma unroll 1
    for (int s = 0; s < 8; s++) {
        float4 acc0 = make_float4(0.f, 0.f, 0.f, 0.f);
        float4 acc1 = make_float4(0.f, 0.f, 0.f, 0.f);
        const u64* bp = g_bf + s * 64 + lane;
        #pragma unroll
        for (int kt = 0; kt < 5; kt++) {
            const u64 v0 = bp[kt * 512];
            const u64 v1 = bp[kt * 512 + 32];
            mma_f16(acc0, afr[kt], (u32)v0, (u32)(v0 >> 32));
            mma_f16(acc1, afr[kt], (u32)v1, (u32)(v1 >> 32));
        }
        // epilogue strip: relu + float4 store (cols permuted in pack_b so
        // {acc0.x,acc0.y,acc1.x,acc1.y} are 4 contiguous output cols)
        const int c0 = s * 16 + t4;
        float4 o;
        o.x = fmaxf(acc0.x, 0.f); o.y = fmaxf(acc0.y, 0.f);
        o.z = fmaxf(acc1.x, 0.f); o.w = fmaxf(acc1.y, 0.f);
        *(float4*)(ob + rLo * CC + c0) = o;
        o.x = fmaxf(acc0.z, 0.f); o.y = fmaxf(acc0.w, 0.f);
        o.z = fmaxf(acc1.z, 0.f); o.w = fmaxf(acc1.w, 0.f);
        *(float4*)(ob + rHi * CC + c0) = o;
    }
    __syncwarp();

    // ---- phase 3: rare inner matvec (deg<5 only, ~3.8% of nodes) ----
    for (int mi = 0; mi < 16; mi++) {
        const int m = w * 16 + mi;
        const int deg = s_deg[m];            // warp-uniform
        if (deg < DD) {
            const int e0 = ge[m*DD+0], e1 = ge[m*DD+1], e2 = ge[m*DD+2],
                      e3 = ge[m*DD+3], e4 = ge[m*DD+4];
            // build X = [summed_atoms | summed_bonds] in per-warp scratch
            #pragma unroll
            for (int rep = 0; rep < 3; rep++) {
                const int f = lane + rep * 32;
                if (f < FA) {
                    float s = 0.f;
                    if (e0 >= 0) s += f16f(aF[e0*KP + f]);
                    if (e1 >= 0) s += f16f(aF[e1*KP + f]);
                    if (e2 >= 0) s += f16f(aF[e2*KP + f]);
                    if (e3 >= 0) s += f16f(aF[e3*KP + f]);
                    if (e4 >= 0) s += f16f(aF[e4*KP + f]);
                    s_xbuf[w * FAN + f] = s;
                } else if (f < FAN) {
                    s_xbuf[w * FAN + f] = s_sb[m * FB + (f - FA)];
                }
            }
            __syncwarp();
            const int c = lane * 4;
            const float* wp = Wi + ((size_t)deg * FAN) * CC + c;
            float4 acc = *(const float4*)(bi + deg * CC + c);
            const float* xr = s_xbuf + w * FAN;
            #pragma unroll 4
            for (int k = 0; k < FAN; k++) {
                const float xv = xr[k];
                const float4 w4 = *(const float4*)(wp + k * CC);
                acc.x += xv * w4.x; acc.y += xv * w4.y;
                acc.z += xv * w4.z; acc.w += xv * w4.w;
            }
            float4* outp = (float4*)(out + ((size_t)b * MM + m) * CC + c);
            float4 o = *outp;
            o.x += fmaxf(acc.x, 0.f); o.y += fmaxf(acc.y, 0.f);
            o.z += fmaxf(acc.z, 0.f); o.w += fmaxf(acc.w, 0.f);
            *outp = o;
            __syncwarp();
        }
    }
}

extern "C" void kernel_launch(void* const* d_in, const int* in_sizes, int n_in,
                              void* d_out, int out_size) {
    const float* atoms = (const float*)d_in[0];
    const float* bonds = (const float*)d_in[1];
    const int*   edges = (const int*)  d_in[2];
    const float* Wi    = (const float*)d_in[3];
    const float* bi    = (const float*)d_in[4];
    const float* Ws    = (const float*)d_in[5];
    const float* bs    = (const float*)d_in[6];
    float* out = (float*)d_out;

    const int B = in_sizes[0] / (MM * FA);

    pack_b_kernel<<<10, 256>>>(Ws, bs);

    cudaFuncSetAttribute(tga_kernel,
                         cudaFuncAttributeMaxDynamicSharedMemorySize, SMEM_BYTES);
    tga_kernel<<<B, 256, SMEM_BYTES>>>(atoms, bonds, edges, Wi, bi, out);
}

// round 13
// speedup vs baseline: 1.4090x; 1.0237x over previous
#include <cuda_runtime.h>
#include <cuda_fp16.h>
#include <cstdint>

#define MM 128
#define DD 5
#define FA 62
#define FB 6
#define FAN 68
#define CC 128
#define KP 88            /* A-tile K stride in halves (176B, conflict-free ldmatrix) */

// ---- smem byte offsets ----
#define SB_SB    0                      /* s_sb   f32 [128][6]  = 3072  */
#define SB_DEG   3072                   /* s_deg  int [128]     = 512   */
#define SB_XBUF  3584                   /* s_xbuf f32 [8][68]   = 2176  */
#define SB_A     5760                   /* u16 [128][88] = 22528 */
#define SMEM_BYTES (SB_A + 22528)       /* 28288 B */

typedef unsigned int u32;
typedef unsigned short u16;
typedef unsigned long long u64;

// Pre-packed fp16 B fragments (column-PERMUTED so epilogue stores are float4):
// index = (kt*16 + n8)*32 + lane ; strip s = n8>>1, tile j = n8&1, c = lane>>2
// logical col n = s*16 + (c>>1)*4 + j*2 + (c&1)
__device__ u64 g_bf[2560];

__device__ __forceinline__ uint32_t smem_u32(const void* p) {
    uint32_t a;
    asm("{ .reg .u64 t; cvta.to.shared.u64 t, %1; cvt.u32.u64 %0, t; }" : "=r"(a) : "l"(p));
    return a;
}
__device__ __forceinline__ uint4 ldm_x4(uint32_t addr) {
    uint4 r;
    asm volatile("ldmatrix.sync.aligned.m8n8.x4.shared.b16 {%0,%1,%2,%3}, [%4];"
                 : "=r"(r.x), "=r"(r.y), "=r"(r.z), "=r"(r.w) : "r"(addr));
    return r;
}
__device__ __forceinline__ void mma_f16(float4& c, const uint4& a, u32 b0, u32 b1) {
    asm volatile(
        "mma.sync.aligned.m16n8k16.row.col.f32.f16.f16.f32 "
        "{%0,%1,%2,%3},{%4,%5,%6,%7},{%8,%9},{%0,%1,%2,%3};"
        : "+f"(c.x), "+f"(c.y), "+f"(c.z), "+f"(c.w)
        : "r"(a.x), "r"(a.y), "r"(a.z), "r"(a.w), "r"(b0), "r"(b1));
}
__device__ __forceinline__ u16 h16(float v) {
    return __half_as_ushort(__float2half_rn(v));
}
__device__ __forceinline__ float f16f(u16 v) {
    return __half2float(__ushort_as_half(v));
}
__device__ __forceinline__ u32 pairh(float a, float b) {
    const __half2 h = __floats2half2_rn(a, b);
    return *(const u32*)&h;
}

// ---- setup kernel: pack Ws|bs into fragment-ordered fp16 (col-permuted) ----
__global__ void pack_b_kernel(const float* __restrict__ Ws, const float* __restrict__ bs) {
    const int idx = blockIdx.x * blockDim.x + threadIdx.x;
    if (idx >= 2560) return;
    const int l    = idx & 31;
    const int tile = idx >> 5;         // kt*16 + n8
    const int kt   = tile >> 4;
    const int n8   = tile & 15;
    const int s    = n8 >> 1;          // col strip (16 cols)
    const int j    = n8 & 1;           // tile within strip
    const int c    = l >> 2, t = l & 3;
    // permuted logical column: thread t owns 4 contiguous cols s*16+4t.. in the strip
    const int n    = s * 16 + (c >> 1) * 4 + j * 2 + (c & 1);
    const int k0   = kt * 16 + 2 * t;
    const int ks[4] = { k0, k0 + 1, k0 + 8, k0 + 9 };
    u16 h[4];
    #pragma unroll
    for (int q = 0; q < 4; q++) {
        const int k = ks[q];
        float v = 0.f;
        if (k < FAN)       v = Ws[k * CC + n];
        else if (k == FAN) v = bs[n];
        h[q] = h16(v);
    }
    g_bf[idx] = (u64)((u32)h[0] | ((u32)h[1] << 16))
              | ((u64)((u32)h[2] | ((u32)h[3] << 16)) << 32);
}

__global__ __launch_bounds__(256, 5)
void tga_kernel(const float* __restrict__ atoms,
                const float* __restrict__ bonds,
                const int*   __restrict__ edges,
                const float* __restrict__ Wi,   // (D, FAN, CC)
                const float* __restrict__ bi,   // (D, CC)
                float* __restrict__ out)        // (B, MM, CC)
{
    extern __shared__ char smem[];
    float* s_sb   = (float*)(smem + SB_SB);     // summed bonds [128][6]
    int*   s_deg  = (int*)(smem + SB_DEG);
    float* s_xbuf = (float*)(smem + SB_XBUF);   // per-warp X scratch [8][68]
    u16*   aF     = (u16*)(smem + SB_A);        // V tile fp16 [128][KP]

    const int b    = blockIdx.x;
    const int tid  = threadIdx.x;
    const int w    = tid >> 5;
    const int lane = tid & 31;

    const float* ga = atoms + (size_t)b * (MM * FA);
    const float* gb = bonds + (size_t)b * (MM * DD * FB);
    const int*   ge = edges + (size_t)b * (MM * DD);

    // ---- phase 1a: summed bonds + degree (high MLP) ----
    #pragma unroll
    for (int rep = 0; rep < 3; rep++) {
        const int i = rep * 256 + tid;
        const int m = i / FB, f = i - m * FB;
        const float* bp = gb + m * (DD * FB) + f;
        s_sb[i] = bp[0] + bp[6] + bp[12] + bp[18] + bp[24];
    }
    if (tid < MM) {
        const int* ep = ge + tid * DD;
        s_deg[tid] = (ep[0] >= 0) + (ep[1] >= 0) + (ep[2] >= 0) + (ep[3] >= 0) + (ep[4] >= 0);
    }
    __syncthreads();

    // ---- phase 1b: A tile atoms, COALESCED + high MLP ----
    // linear float2 index i -> row i/31, cols 2*(i%31); gmem addr = ga + 2i (contiguous)
    #pragma unroll 8
    for (int i = tid; i < MM * 31; i += 256) {
        const float2 x = ((const float2*)ga)[i];
        const int row = i / 31;
        const int c2  = i - row * 31;
        *(u32*)(aF + row * KP + 2 * c2) = pairh(x.x, x.y);   // cols 0..61
    }
    // tail cols 62..87: 2 threads per row (bonds | bias | zero-pad)
    {
        const int mr = tid >> 1;                 // 0..127
        u64* arow = (u64*)(aF + mr * KP);
        const float* sb = s_sb + mr * FB;
        if (tid & 1) {
            *(u32*)(aF + mr * KP + 62) = pairh(sb[0], sb[1]);    // cols 62,63
            arow[17] = 0x3C00ull;                                // col 68 = 1.0
            arow[19] = 0;  arow[21] = 0;
        } else {
            arow[16] = (u64)pairh(sb[2], sb[3]) | ((u64)pairh(sb[4], sb[5]) << 32); // 64..67
            arow[18] = 0;  arow[20] = 0;
        }
    }
    __syncthreads();

    // ---- phase 2: warp w -> rows [16w,16w+16); A frags hoisted; 8 col-strips of 16 ----
    const int m0 = w * 16;
    const u32 aAddr = smem_u32(aF);
    const int aRow = m0 + (lane & 7) + ((lane >> 3) & 1) * 8;
    const int aColOff = (lane >> 4) * 8;
    float* ob = out + (size_t)b * (MM * CC);
    const int rLo = m0 + (lane >> 2);
    const int rHi = rLo + 8;
    const int t4  = 4 * (lane & 3);

    uint4 afr[5];
    #pragma unroll
    for (int kt = 0; kt < 5; kt++)
        afr[kt] = ldm_x4(aAddr + (aRow * KP + kt * 16 + aColOff) * 2);

    #pragma unroll 1
    for (int s = 0; s < 8; s++) {
        float4 acc0 = make_float4(0.f, 0.f, 0.f, 0.f);
        float4 acc1 = make_float4(0.f, 0.f, 0.f, 0.f);
        const u64* bp = g_bf + s * 64 + lane;
        #pragma unroll
        for (int kt = 0; kt < 5; kt++) {
            const u64 v0 = bp[kt * 512];
            const u64 v1 = bp[kt * 512 + 32];
            mma_f16(acc0, afr[kt], (u32)v0, (u32)(v0 >> 32));
            mma_f16(acc1, afr[kt], (u32)v1, (u32)(v1 >> 32));
        }
        // epilogue strip: relu + float4 store (cols permuted in pack_b so
        // {acc0.x,acc0.y,acc1.x,acc1.y} are 4 contiguous output cols)
        const int c0 = s * 16 + t4;
        float4 o;
        o.x = fmaxf(acc0.x, 0.f); o.y = fmaxf(acc0.y, 0.f);
        o.z = fmaxf(acc1.x, 0.f); o.w = fmaxf(acc1.y, 0.f);
        *(float4*)(ob + rLo * CC + c0) = o;
        o.x = fmaxf(acc0.z, 0.f); o.y = fmaxf(acc0.w, 0.f);
        o.z = fmaxf(acc1.z, 0.f); o.w = fmaxf(acc1.w, 0.f);
        *(float4*)(ob + rHi * CC + c0) = o;
    }
    __syncwarp();

    // ---- phase 3: rare inner matvec (deg<5 only, ~3.8% of nodes) ----
    for (int mi = 0; mi < 16; mi++) {
        const int m = w * 16 + mi;
        const int deg = s_deg[m];            // warp-uniform
        if (deg < DD) {
            const int e0 = ge[m*DD+0], e1 = ge[m*DD+1], e2 = ge[m*DD+2],
                      e3 = ge[m*DD+3], e4 = ge[m*DD+4];
            // build X = [summed_atoms | summed_bonds] in per-warp scratch
            #pragma unroll
            for (int rep = 0; rep < 3; rep++) {
                const int f = lane + rep * 32;
                if (f < FA) {
                    float s = 0.f;
                    if (e0 >= 0) s += f16f(aF[e0*KP + f]);
                    if (e1 >= 0) s += f16f(aF[e1*KP + f]);
                    if (e2 >= 0) s += f16f(aF[e2*KP + f]);
                    if (e3 >= 0) s += f16f(aF[e3*KP + f]);
                    if (e4 >= 0) s += f16f(aF[e4*KP + f]);
                    s_xbuf[w * FAN + f] = s;
                } else if (f < FAN) {
                    s_xbuf[w * FAN + f] = s_sb[m * FB + (f - FA)];
                }
            }
            __syncwarp();
            const int c = lane * 4;
            const float* wp = Wi + ((size_t)deg * FAN) * CC + c;
            float4 acc = *(const float4*)(bi + deg * CC + c);
            const float* xr = s_xbuf + w * FAN;
            #pragma unroll 4
            for (int k = 0; k < FAN; k++) {
                const float xv = xr[k];
                const float4 w4 = *(const float4*)(wp + k * CC);
                acc.x += xv * w4.x; acc.y += xv * w4.y;
                acc.z += xv * w4.z; acc.w += xv * w4.w;
            }
            float4* outp = (float4*)(out + ((size_t)b * MM + m) * CC + c);
            float4 o = *outp;
            o.x += fmaxf(acc.x, 0.f); o.y += fmaxf(acc.y, 0.f);
            o.z += fmaxf(acc.z, 0.f); o.w += fmaxf(acc.w, 0.f);
            *outp = o;
            __syncwarp();
        }
    }
}

extern "C" void kernel_launch(void* const* d_in, const int* in_sizes, int n_in,
                              void* d_out, int out_size) {
    const float* atoms = (const float*)d_in[0];
    const float* bonds = (const float*)d_in[1];
    const int*   edges = (const int*)  d_in[2];
    const float* Wi    = (const float*)d_in[3];
    const float* bi    = (const float*)d_in[4];
    const float* Ws    = (const float*)d_in[5];
    const float* bs    = (const float*)d_in[6];
    float* out = (float*)d_out;

    const int B = in_sizes[0] / (MM * FA);

    pack_b_kernel<<<10, 256>>>(Ws, bs);

    cudaFuncSetAttribute(tga_kernel,
                         cudaFuncAttributeMaxDynamicSharedMemorySize, SMEM_BYTES);
    tga_kernel<<<B, 256, SMEM_BYTES>>>(atoms, bonds, edges, Wi, bi, out);
}